// round 2
// baseline (speedup 1.0000x reference)
#include <cuda_runtime.h>
#include <math.h>
#include <float.h>

// ---------------- problem dims ----------------
#define BB    64      // batch / timesteps
#define NN    1024    // feature length
#define H16   256
#define H64   1024
#define H128  2048
#define NGATE 8192    // 4*H128

#define LSTM_CTAS 64  // persistent LSTM grid (single wave guaranteed: 64 < 148 SMs)

// ---------------- device scratch (no allocs allowed) ----------------
__device__ float g_x [BB * NN];      // GCN output
__device__ float g_af[BB * H16];     // relu(f)
__device__ float g_ai[BB * H64];     // relu(i)
__device__ float g_z [BB * H128];    // relu(o) = z
__device__ float g_gi[BB * NGATE];   // z @ w_ih.T + b_ih + b_hh
__device__ float g_h [2][H128];      // double-buffered recurrent h
__device__ volatile unsigned g_bar_arrive;
__device__ volatile unsigned g_bar_gen;

__global__ void reset_kernel() { g_bar_arrive = 0u; g_bar_gen = 0u; }

// ---------------- GCN: one block per sample ----------------
__global__ __launch_bounds__(1024) void gcn_kernel(
    const float* __restrict__ inp,
    const float* __restrict__ gc1w, const float* __restrict__ gc1b,
    const float* __restrict__ gc2w, const float* __restrict__ gc2b)
{
    __shared__ float xs[NN];
    __shared__ float s2[NN];
    const int s = blockIdx.x;
    const int i = threadIdx.x;
    xs[i] = inp[s * NN + i];
    __syncthreads();
    const float xi = xs[i];

    // top-4 smallest |xi - xj|, ties -> smaller index (matches jax top_k of -d)
    float d0 = INFINITY, d1 = INFINITY, d2 = INFINITY, d3 = INFINITY;
    int i0 = 0, i1 = 0, i2 = 0, i3 = 0;
    for (int j = 0; j < NN; ++j) {
        float dj = fabsf(xi - xs[j]);
        if (j != i && dj < d3) {
            if (dj < d2) {
                d3 = d2; i3 = i2;
                if (dj < d1) {
                    d2 = d1; i2 = i1;
                    if (dj < d0) { d1 = d0; i1 = i0; d0 = dj; i0 = j; }
                    else         { d1 = dj; i1 = j; }
                } else { d2 = dj; i2 = j; }
            } else { d3 = dj; i3 = j; }
        }
    }

    // S = sum of neighbor x; h_c = relu(gc1w_c*S + gc1b_c); v = sum_c h_c*gc2w_c
    float S = xs[i0] + xs[i1] + xs[i2] + xs[i3];
    float v = 0.f;
#pragma unroll
    for (int c = 0; c < 4; ++c) {
        float hc = fmaxf(gc1w[c] * S + gc1b[c], 0.f);
        v += hc * gc2w[c];
    }
    s2[i] = v;
    __syncthreads();
    g_x[s * NN + i] = s2[i0] + s2[i1] + s2[i2] + s2[i3] + gc2b[0];
}

// ---------------- tiled fp32 GEMM: C[t][r] = act(sum_j A[t][j]*W[r][j] + bias) ----------------
// T must be 64; R, J multiples of 64. Block computes 64x64 tile, 256 threads, 4x4 microtile.
template <int T, int R, int J, bool RELU, bool HASB2>
__global__ __launch_bounds__(256) void gemm_kernel(
    const float* __restrict__ A,   // [T][J]
    const float* __restrict__ W,   // [R][J]
    const float* __restrict__ b1,  // [R]
    const float* __restrict__ b2,  // [R] or null
    float* __restrict__ C)         // [T][R]
{
    __shared__ float As[64][65];
    __shared__ float Ws[64][65];
    const int br0 = blockIdx.x * 64;
    const int tid = threadIdx.x;
    const int tq = tid & 15;   // t = tq + 16*a
    const int rq = tid >> 4;   // r = rq + 16*b

    float acc[4][4];
#pragma unroll
    for (int a = 0; a < 4; ++a)
#pragma unroll
        for (int b = 0; b < 4; ++b) acc[a][b] = 0.f;

    for (int j0 = 0; j0 < J; j0 += 64) {
        for (int idx = tid; idx < 64 * 64; idx += 256) {
            int row = idx >> 6, kk = idx & 63;
            As[row][kk] = A[row * J + j0 + kk];
            Ws[row][kk] = W[(size_t)(br0 + row) * J + j0 + kk];
        }
        __syncthreads();
#pragma unroll 16
        for (int kk = 0; kk < 64; ++kk) {
            float av[4], wv[4];
#pragma unroll
            for (int a = 0; a < 4; ++a) av[a] = As[tq + 16 * a][kk];
#pragma unroll
            for (int b = 0; b < 4; ++b) wv[b] = Ws[rq + 16 * b][kk];
#pragma unroll
            for (int a = 0; a < 4; ++a)
#pragma unroll
                for (int b = 0; b < 4; ++b) acc[a][b] += av[a] * wv[b];
        }
        __syncthreads();
    }

#pragma unroll
    for (int b = 0; b < 4; ++b) {
        int r = br0 + rq + 16 * b;
        float bias = b1[r];
        if (HASB2) bias += b2[r];
#pragma unroll
        for (int a = 0; a < 4; ++a) {
            int t = tq + 16 * a;
            float vv = acc[a][b] + bias;
            if (RELU) vv = fmaxf(vv, 0.f);
            C[t * R + r] = vv;
        }
    }
}

// ---------------- grid-wide barrier (single-wave persistent kernel) ----------------
__device__ __forceinline__ void grid_barrier(int nct, unsigned& gen)
{
    __syncthreads();
    unsigned target = ++gen;
    if (threadIdx.x == 0) {
        __threadfence();
        unsigned a = atomicAdd((unsigned*)&g_bar_arrive, 1u);
        if (a == (unsigned)nct - 1u) {
            g_bar_arrive = 0u;            // reset BEFORE publishing generation
            __threadfence();
            atomicExch((unsigned*)&g_bar_gen, target);
        } else {
            while (g_bar_gen < target) { __nanosleep(64); }
        }
        __threadfence();
    }
    __syncthreads();
}

__device__ __forceinline__ float sigmoidf_(float x) { return 1.f / (1.f + expf(-x)); }

// ---------------- persistent LSTM: LSTM_CTAS CTAs, each owns 32 units (128 gate rows) ----------------
__global__ __launch_bounds__(1024, 1) void lstm_kernel(
    const float* __restrict__ w_hh,  // [8192][2048] row-major
    float* __restrict__ out)         // [64][2048]
{
    __shared__ float h_sm[H128];
    __shared__ float g_sm[128];
    __shared__ float c_sm[32];
    const int tid  = threadIdx.x;
    const int nct  = gridDim.x;
    const int ub   = blockIdx.x * 32;         // first unit owned by this CTA
    const int warp = tid >> 5, lane = tid & 31;
    unsigned gen = 0;

    if (tid < 32) { c_sm[tid] = 0.f; g_h[0][ub + tid] = 0.f; }
    __threadfence();
    grid_barrier(nct, gen);

    for (int t = 0; t < BB; ++t) {
        // pull h (state t) into SMEM; __ldcg: L1 not coherent across CTAs
        const float4* hb = (const float4*)g_h[t & 1];
        for (int idx = tid; idx < H128 / 4; idx += 1024)
            ((float4*)h_sm)[idx] = __ldcg(hb + idx);
        __syncthreads();

        // 32 warps x 4 rows = 128 gate rows; local row lr -> global row = gate*2048 + unit
#pragma unroll
        for (int rr = 0; rr < 4; ++rr) {
            int lr   = warp * 4 + rr;                       // 0..127
            int row  = (lr >> 5) * H128 + ub + (lr & 31);   // gate = lr/32, unit = ub + lr%32
            const float4* wr = (const float4*)(w_hh + (size_t)row * H128);
            float acc = 0.f;
#pragma unroll
            for (int it = 0; it < 16; ++it) {
                float4 w4 = wr[lane + it * 32];
                float4 h4 = ((const float4*)h_sm)[lane + it * 32];
                acc += w4.x * h4.x + w4.y * h4.y + w4.z * h4.z + w4.w * h4.w;
            }
#pragma unroll
            for (int o = 16; o > 0; o >>= 1) acc += __shfl_xor_sync(0xffffffffu, acc, o);
            if (lane == 0) g_sm[lr] = acc + g_gi[t * NGATE + row];
        }
        __syncthreads();

        if (tid < 32) {
            float ig = g_sm[tid], fg = g_sm[32 + tid], gg = g_sm[64 + tid], og = g_sm[96 + tid];
            float c = sigmoidf_(fg) * c_sm[tid] + sigmoidf_(ig) * tanhf(gg);
            float h = sigmoidf_(og) * tanhf(c);
            c_sm[tid] = c;
            g_h[(t + 1) & 1][ub + tid] = h;
            out[t * H128 + ub + tid] = h;
            __threadfence();
        }
        grid_barrier(nct, gen);
    }
}

// ---------------- launch ----------------
extern "C" void kernel_launch(void* const* d_in, const int* in_sizes, int n_in,
                              void* d_out, int out_size)
{
    const float* inp  = (const float*)d_in[0];
    // d_in[1] Hidden_State, d_in[2] Cell_State: zeros, start state handled in-kernel
    const float* gc1w = (const float*)d_in[3];
    const float* gc1b = (const float*)d_in[4];
    const float* gc2w = (const float*)d_in[5];
    const float* gc2b = (const float*)d_in[6];
    const float* flw  = (const float*)d_in[7];
    const float* flb  = (const float*)d_in[8];
    const float* ilw  = (const float*)d_in[9];
    const float* ilb  = (const float*)d_in[10];
    const float* olw  = (const float*)d_in[11];
    const float* olb  = (const float*)d_in[12];
    const float* wih  = (const float*)d_in[13];
    const float* whh  = (const float*)d_in[14];
    const float* bih  = (const float*)d_in[15];
    const float* bhh  = (const float*)d_in[16];
    float* out = (float*)d_out;

    void *px, *paf, *pai, *pz, *pgi;
    cudaGetSymbolAddress(&px,  g_x);
    cudaGetSymbolAddress(&paf, g_af);
    cudaGetSymbolAddress(&pai, g_ai);
    cudaGetSymbolAddress(&pz,  g_z);
    cudaGetSymbolAddress(&pgi, g_gi);

    reset_kernel<<<1, 1>>>();
    gcn_kernel<<<BB, NN>>>(inp, gc1w, gc1b, gc2w, gc2b);
    gemm_kernel<BB, H16,  NN,   true,  false><<<H16  / 64, 256>>>((const float*)px,  flw, flb, nullptr, (float*)paf);
    gemm_kernel<BB, H64,  H16,  true,  false><<<H64  / 64, 256>>>((const float*)paf, ilw, ilb, nullptr, (float*)pai);
    gemm_kernel<BB, H128, H64,  true,  false><<<H128 / 64, 256>>>((const float*)pai, olw, olb, nullptr, (float*)pz);
    gemm_kernel<BB, NGATE, H128, false, true ><<<NGATE / 64, 256>>>((const float*)pz, wih, bih, bhh, (float*)pgi);
    lstm_kernel<<<LSTM_CTAS, 1024>>>(whh, out);
}

// round 3
// speedup vs baseline: 2.2163x; 2.2163x over previous
#include <cuda_runtime.h>
#include <cuda_fp16.h>
#include <math.h>
#include <float.h>

// ---------------- problem dims ----------------
#define BB    64      // batch / timesteps
#define NN    1024    // feature length
#define H16   256
#define H64   1024
#define H128  2048
#define NGATE 8192    // 4*H128

#define NCTA_MAX 148

// ---------------- device scratch (no allocs allowed) ----------------
__device__ float g_x [BB * NN];         // GCN output
__device__ float g_af[BB * H16];        // relu(f)
__device__ float g_ai[BB * H64];        // relu(i)
__device__ float g_z [BB * H128];       // relu(o) = z
__device__ float g_gi[BB * NGATE];      // z @ w_ih.T + b_ih + b_hh
__device__ float g_part[1 << 20];       // split-K partials (max 4MB)
__device__ __align__(16) __half g_whh[NGATE * H128];  // fp16 w_hh (32MB)
__device__ float g_h [2][H128];         // double-buffered recurrent h
__device__ unsigned g_slot[NCTA_MAX * 8];  // spread barrier slots (32B apart)

__global__ void reset_kernel() {
    for (int i = threadIdx.x; i < NCTA_MAX * 8; i += blockDim.x) g_slot[i] = 0u;
}

// ---------------- w_hh fp32 -> fp16 ----------------
__global__ __launch_bounds__(1024) void convert_whh(const float* __restrict__ w)
{
    const int total = NGATE * H128 / 2;          // half2 count
    const float2* src = (const float2*)w;
    __half2* dst = (__half2*)g_whh;
    int stride = gridDim.x * blockDim.x;
    for (int k = blockIdx.x * blockDim.x + threadIdx.x; k < total; k += stride) {
        float2 v = src[k];
        dst[k] = __floats2half2_rn(v.x, v.y);
    }
}

// ---------------- GCN: one block per sample ----------------
__global__ __launch_bounds__(1024) void gcn_kernel(
    const float* __restrict__ inp,
    const float* __restrict__ gc1w, const float* __restrict__ gc1b,
    const float* __restrict__ gc2w, const float* __restrict__ gc2b)
{
    __shared__ float xs[NN];
    __shared__ float s2[NN];
    const int s = blockIdx.x;
    const int i = threadIdx.x;
    xs[i] = inp[s * NN + i];
    __syncthreads();
    const float xi = xs[i];

    // top-4 smallest |xi - xj|, ties -> smaller index (matches jax top_k of -d)
    float d0 = INFINITY, d1 = INFINITY, d2 = INFINITY, d3 = INFINITY;
    int i0 = 0, i1 = 0, i2 = 0, i3 = 0;
    for (int j = 0; j < NN; ++j) {
        float dj = fabsf(xi - xs[j]);
        if (j != i && dj < d3) {
            if (dj < d2) {
                d3 = d2; i3 = i2;
                if (dj < d1) {
                    d2 = d1; i2 = i1;
                    if (dj < d0) { d1 = d0; i1 = i0; d0 = dj; i0 = j; }
                    else         { d1 = dj; i1 = j; }
                } else { d2 = dj; i2 = j; }
            } else { d3 = dj; i3 = j; }
        }
    }

    float S = xs[i0] + xs[i1] + xs[i2] + xs[i3];
    float v = 0.f;
#pragma unroll
    for (int c = 0; c < 4; ++c) {
        float hc = fmaxf(gc1w[c] * S + gc1b[c], 0.f);
        v += hc * gc2w[c];
    }
    s2[i] = v;
    __syncthreads();
    g_x[s * NN + i] = s2[i0] + s2[i1] + s2[i2] + s2[i3] + gc2b[0];
}

// ---------------- split-K tiled GEMM: part[kc][t][r] = sum_{j in chunk} A[t][j]*W[r][j] ----------------
// Tile 64(T) x 32(R'), 128 threads, micro 4x4 (tq 0..15 -> t, rq 0..7 -> r).
template <int R, int J, int KC>
__global__ __launch_bounds__(128) void gemm_sk(
    const float* __restrict__ A,   // [64][J]
    const float* __restrict__ W,   // [R][J]
    float* __restrict__ part)      // [KC][64][R]
{
    __shared__ float As[64][33];
    __shared__ float Ws[32][33];
    const int JC  = J / KC;
    const int kc  = blockIdx.y;
    const int br0 = blockIdx.x * 32;
    const int tid = threadIdx.x;
    const int tq  = tid & 15;
    const int rq  = tid >> 4;     // 0..7

    float acc[4][4];
#pragma unroll
    for (int a = 0; a < 4; ++a)
#pragma unroll
        for (int b = 0; b < 4; ++b) acc[a][b] = 0.f;

    const int j_end = (kc + 1) * JC;
    for (int j0 = kc * JC; j0 < j_end; j0 += 32) {
#pragma unroll
        for (int idx = tid; idx < 64 * 32; idx += 128) {
            int row = idx >> 5, col = idx & 31;
            As[row][col] = A[row * J + j0 + col];
        }
#pragma unroll
        for (int idx = tid; idx < 32 * 32; idx += 128) {
            int row = idx >> 5, col = idx & 31;
            Ws[row][col] = W[(size_t)(br0 + row) * J + j0 + col];
        }
        __syncthreads();
#pragma unroll
        for (int kk = 0; kk < 32; ++kk) {
            float av[4], wv[4];
#pragma unroll
            for (int a = 0; a < 4; ++a) av[a] = As[tq + 16 * a][kk];
#pragma unroll
            for (int b = 0; b < 4; ++b) wv[b] = Ws[rq + 8 * b][kk];
#pragma unroll
            for (int a = 0; a < 4; ++a)
#pragma unroll
                for (int b = 0; b < 4; ++b) acc[a][b] += av[a] * wv[b];
        }
        __syncthreads();
    }

#pragma unroll
    for (int a = 0; a < 4; ++a)
#pragma unroll
        for (int b = 0; b < 4; ++b)
            part[(size_t)kc * 64 * R + (tq + 16 * a) * R + br0 + rq + 8 * b] = acc[a][b];
}

// reduce partials: C[t][r] = act(sum_kc part + b1 [+ b2])
template <int R, int KC, bool RELU, bool HASB2>
__global__ __launch_bounds__(256) void reduce_k(
    const float* __restrict__ part,
    const float* __restrict__ b1, const float* __restrict__ b2,
    float* __restrict__ C)
{
    int i = blockIdx.x * 256 + threadIdx.x;
    if (i >= 64 * R) return;
    int r = i % R;
    float s = 0.f;
#pragma unroll
    for (int kc = 0; kc < KC; ++kc) s += part[(size_t)kc * 64 * R + i];
    s += b1[r];
    if (HASB2) s += b2[r];
    if (RELU) s = fmaxf(s, 0.f);
    C[i] = s;
}

__device__ __forceinline__ float sigmoidf_(float x) { return 1.f / (1.f + expf(-x)); }

// ---------------- persistent LSTM ----------------
// grid = ncta (= SM count, single wave guaranteed). Runtime unit partition:
// base = 2048/ncta, first rem CTAs get base+1 units. Each unit = 4 gate rows.
__global__ __launch_bounds__(1024, 1) void lstm_kernel(float* __restrict__ out, int ncta)
{
    __shared__ float h_sm[H128];
    __shared__ float g_sm[136];
    __shared__ float c_sm[34];
    const int tid  = threadIdx.x;
    const int bid  = blockIdx.x;
    const int warp = tid >> 5, lane = tid & 31;

    const int base = H128 / ncta;
    const int rem  = H128 - base * ncta;
    const int nu   = (bid < rem) ? base + 1 : base;
    const int u0   = bid * base + min(bid, rem);
    const int ROWS = 4 * nu;

    // up to 4 rows per warp: lr = warp + 32k
    int cnt = 0;
    int rowg[4];
    const uint4* wp[4];
#pragma unroll
    for (int k = 0; k < 4; ++k) {
        int lr = warp + 32 * k;
        if (lr < ROWS) {
            int g = lr / nu, ui = lr - g * nu;
            rowg[cnt] = g * H128 + u0 + ui;
            wp[cnt]   = (const uint4*)(g_whh + (size_t)rowg[cnt] * H128);
            ++cnt;
        }
    }

    volatile unsigned* slots = (volatile unsigned*)g_slot;

    if (tid < nu) { c_sm[tid] = 0.f; g_h[0][u0 + tid] = 0.f; }
    __syncthreads();
    if (tid == 0) { __threadfence(); slots[bid * 8] = 1u; }
    if (tid < ncta) { while (slots[tid * 8] < 1u) {} }
    __threadfence();
    __syncthreads();

    for (int t = 0; t < BB; ++t) {
        const float4* hb = (const float4*)g_h[t & 1];
        if (tid < H128 / 4) ((float4*)h_sm)[tid] = __ldcg(hb + tid);
        __syncthreads();

        float acc[4] = {0.f, 0.f, 0.f, 0.f};
        const float4* hs4 = (const float4*)h_sm;
#pragma unroll
        for (int i = 0; i < 8; ++i) {
            int o = lane + 32 * i;                 // uint4 index: 8 halfs each
            float4 ha = hs4[o * 2];
            float4 hb4 = hs4[o * 2 + 1];
#pragma unroll
            for (int k = 0; k < 4; ++k) {
                if (k < cnt) {
                    uint4 w4 = wp[k][o];
                    const __half2* hp = (const __half2*)&w4;
                    float2 f;
                    f = __half22float2(hp[0]); acc[k] += f.x * ha.x  + f.y * ha.y;
                    f = __half22float2(hp[1]); acc[k] += f.x * ha.z  + f.y * ha.w;
                    f = __half22float2(hp[2]); acc[k] += f.x * hb4.x + f.y * hb4.y;
                    f = __half22float2(hp[3]); acc[k] += f.x * hb4.z + f.y * hb4.w;
                }
            }
        }
#pragma unroll
        for (int k = 0; k < 4; ++k) {
#pragma unroll
            for (int o = 16; o > 0; o >>= 1) acc[k] += __shfl_xor_sync(0xffffffffu, acc[k], o);
        }
        if (lane == 0) {
#pragma unroll
            for (int k = 0; k < 4; ++k)
                if (k < cnt) g_sm[warp + 32 * k] = acc[k] + g_gi[t * NGATE + rowg[k]];
        }
        __syncthreads();

        if (tid < nu) {
            float ig = g_sm[tid], fg = g_sm[nu + tid], gg = g_sm[2 * nu + tid], og = g_sm[3 * nu + tid];
            float c = sigmoidf_(fg) * c_sm[tid] + sigmoidf_(ig) * tanhf(gg);
            float h = sigmoidf_(og) * tanhf(c);
            c_sm[tid] = c;
            g_h[(t + 1) & 1][u0 + tid] = h;
            out[t * H128 + u0 + tid] = h;
        }
        __syncthreads();
        if (tid == 0) { __threadfence(); slots[bid * 8] = (unsigned)(t + 2); }
        if (tid < ncta) { while (slots[tid * 8] < (unsigned)(t + 2)) {} }
        __threadfence();
        __syncthreads();
    }
}

// ---------------- launch ----------------
extern "C" void kernel_launch(void* const* d_in, const int* in_sizes, int n_in,
                              void* d_out, int out_size)
{
    const float* inp  = (const float*)d_in[0];
    const float* gc1w = (const float*)d_in[3];
    const float* gc1b = (const float*)d_in[4];
    const float* gc2w = (const float*)d_in[5];
    const float* gc2b = (const float*)d_in[6];
    const float* flw  = (const float*)d_in[7];
    const float* flb  = (const float*)d_in[8];
    const float* ilw  = (const float*)d_in[9];
    const float* ilb  = (const float*)d_in[10];
    const float* olw  = (const float*)d_in[11];
    const float* olb  = (const float*)d_in[12];
    const float* wih  = (const float*)d_in[13];
    const float* whh  = (const float*)d_in[14];
    const float* bih  = (const float*)d_in[15];
    const float* bhh  = (const float*)d_in[16];
    float* out = (float*)d_out;

    void *px, *paf, *pai, *pz, *pgi, *ppart;
    cudaGetSymbolAddress(&px,    g_x);
    cudaGetSymbolAddress(&paf,   g_af);
    cudaGetSymbolAddress(&pai,   g_ai);
    cudaGetSymbolAddress(&pz,    g_z);
    cudaGetSymbolAddress(&pgi,   g_gi);
    cudaGetSymbolAddress(&ppart, g_part);
    float* part = (float*)ppart;

    int sms = 0;
    cudaDeviceGetAttribute(&sms, cudaDevAttrMultiProcessorCount, 0);
    int ncta = sms;
    if (ncta > NCTA_MAX) ncta = NCTA_MAX;
    if (ncta < 64) ncta = 64;   // nu <= 32 -> ROWS <= 128, 4 rows/warp max

    reset_kernel<<<1, 256>>>();
    convert_whh<<<2048, 1024>>>(whh);
    gcn_kernel<<<BB, NN>>>(inp, gc1w, gc1b, gc2w, gc2b);

    // fl: [64,256] = x[64,1024] @ fl_w.T ; relu
    gemm_sk<H16, NN, 16><<<dim3(H16 / 32, 16), 128>>>((const float*)px, flw, part);
    reduce_k<H16, 16, true, false><<<(64 * H16 + 255) / 256, 256>>>(part, flb, nullptr, (float*)paf);
    // il: [64,1024] = af[64,256] @ il_w.T ; relu
    gemm_sk<H64, H16, 4><<<dim3(H64 / 32, 4), 128>>>((const float*)paf, ilw, part);
    reduce_k<H64, 4, true, false><<<(64 * H64 + 255) / 256, 256>>>(part, ilb, nullptr, (float*)pai);
    // ol: [64,2048] = ai[64,1024] @ ol_w.T ; relu -> z
    gemm_sk<H128, H64, 4><<<dim3(H128 / 32, 4), 128>>>((const float*)pai, olw, part);
    reduce_k<H128, 4, true, false><<<(64 * H128 + 255) / 256, 256>>>(part, olb, nullptr, (float*)pz);
    // gate: [64,8192] = z[64,2048] @ w_ih.T + b_ih + b_hh
    gemm_sk<NGATE, H128, 2><<<dim3(NGATE / 32, 2), 128>>>((const float*)pz, wih, part);
    reduce_k<NGATE, 2, false, true><<<(64 * NGATE + 255) / 256, 256>>>(part, bih, bhh, (float*)pgi);

    lstm_kernel<<<ncta, 1024>>>(out, ncta);
}